// round 1
// baseline (speedup 1.0000x reference)
#include <cuda_runtime.h>

#define NE   100
#define D    240
#define D4   (D / 4)          // 60
#define MROWS 4096
#define HID  256
#define NC   112
#define EDIM 64
#define GRID2 296             // 2 persistent CTAs per SM (148 SMs on B200)

// Expanded gates scratch: [NE, D] floats (96 KB). __device__ global = allowed scratch.
__device__ float g_gf[NE * D];

// Closed-form GATE_IDX for IRREPS [(64,1),(32,3),(16,5)]
__device__ __forceinline__ int gate_idx(int t) {
    if (t < 64)  return t;
    if (t < 160) return 64 + (t - 64) / 3;
    return 96 + (t - 160) / 5;
}

// ---------------- Kernel 1: tiny MLP, one block per edge ----------------
__global__ void mlp_kernel(const float* __restrict__ e_feat,
                           const float* __restrict__ W1, const float* __restrict__ b1,
                           const float* __restrict__ W2, const float* __restrict__ b2,
                           const float* __restrict__ W3, const float* __restrict__ b3) {
    __shared__ float sh_a[HID];   // holds e-row (first 64), then h2
    __shared__ float sh_b[HID];   // holds h1
    __shared__ float sh_g[NC];    // final gates

    const int e = blockIdx.x;
    const int tid = threadIdx.x;

    if (tid < EDIM) sh_a[tid] = e_feat[e * EDIM + tid];
    __syncthreads();

    // h1 = relu(e @ W1 + b1), W1 is [64,256] row-major; thread tid owns hidden unit tid
    float acc = b1[tid];
    #pragma unroll
    for (int k = 0; k < EDIM; ++k)
        acc = fmaf(sh_a[k], W1[k * HID + tid], acc);
    sh_b[tid] = fmaxf(acc, 0.0f);
    __syncthreads();

    // h2 = relu(h1 @ W2 + b2), W2 [256,256]
    float acc2 = b2[tid];
    #pragma unroll 8
    for (int k = 0; k < HID; ++k)
        acc2 = fmaf(sh_b[k], W2[k * HID + tid], acc2);
    sh_a[tid] = fmaxf(acc2, 0.0f);
    __syncthreads();

    // gates = h2 @ W3 + b3, W3 [256,112]
    if (tid < NC) {
        float a3 = b3[tid];
        #pragma unroll 8
        for (int k = 0; k < HID; ++k)
            a3 = fmaf(sh_a[k], W3[k * NC + tid], a3);
        sh_g[tid] = a3;
    }
    __syncthreads();

    // Expand 112 -> 240 via GATE_IDX and write to global scratch
    if (tid < D) g_gf[e * D + tid] = sh_g[gate_idx(tid)];
}

// ---------------- Kernel 2: streaming broadcast multiply ----------------
// out[m, e, d] = x[m, d] * gf[e, d]   (393 MB of writes -> DRAM-bound)
// Persistent blocks: gates_full cached in shared ONCE per block, then loop m.
__global__ void __launch_bounds__(512) bcast_kernel(const float* __restrict__ x,
                                                    float* __restrict__ out) {
    extern __shared__ float4 sh_gf4[];   // NE*D4 = 6000 float4 = 96 KB
    const float4* gf4 = reinterpret_cast<const float4*>(g_gf);

    for (int i = threadIdx.x; i < NE * D4; i += blockDim.x)
        sh_gf4[i] = gf4[i];
    __syncthreads();

    const float4* x4 = reinterpret_cast<const float4*>(x);
    float4* out4 = reinterpret_cast<float4*>(out);

    for (int m = blockIdx.x; m < MROWS; m += gridDim.x) {
        const float4* __restrict__ xr = x4 + m * D4;       // 60 float4, stays hot in L1
        float4* __restrict__ orow = out4 + (size_t)m * (NE * D4);
        for (int i = threadIdx.x; i < NE * D4; i += blockDim.x) {
            const int d4 = i % D4;
            const float4 g = sh_gf4[i];
            const float4 xv = __ldg(&xr[d4]);
            float4 r;
            r.x = g.x * xv.x;
            r.y = g.y * xv.y;
            r.z = g.z * xv.z;
            r.w = g.w * xv.w;
            orow[i] = r;   // fully coalesced float4 streaming store
        }
    }
}

extern "C" void kernel_launch(void* const* d_in, const int* in_sizes, int n_in,
                              void* d_out, int out_size) {
    const float* x      = (const float*)d_in[0];
    const float* e_feat = (const float*)d_in[1];
    const float* W1     = (const float*)d_in[2];
    const float* b1     = (const float*)d_in[3];
    const float* W2     = (const float*)d_in[4];
    const float* b2     = (const float*)d_in[5];
    const float* W3     = (const float*)d_in[6];
    const float* b3     = (const float*)d_in[7];
    float* out = (float*)d_out;

    mlp_kernel<<<NE, HID>>>(e_feat, W1, b1, W2, b2, W3, b3);

    const int smem = NE * D * (int)sizeof(float);   // 96000 bytes
    cudaFuncSetAttribute(bcast_kernel, cudaFuncAttributeMaxDynamicSharedMemorySize, smem);
    bcast_kernel<<<GRID2, 512, smem>>>(x, out);
}

// round 2
// speedup vs baseline: 1.3947x; 1.3947x over previous
#include <cuda_runtime.h>

#define NE   100
#define D    240
#define D4   (D / 4)          // 60
#define MROWS 4096
#define HID  256
#define NC   112
#define EDIM 64
#define GRID2 296             // 2 persistent CTAs per SM

// Expanded gates scratch: [NE, D] floats (96 KB).
__device__ float g_gf[NE * D];

// Closed-form GATE_IDX for IRREPS [(64,1),(32,3),(16,5)]
__device__ __forceinline__ int gate_idx(int t) {
    if (t < 64)  return t;
    if (t < 160) return 64 + (t - 64) / 3;
    return 96 + (t - 160) / 5;
}

// ---------------- Kernel 1: tiny MLP, one block per edge, 4-way split-K ----
__global__ void __launch_bounds__(1024) mlp_kernel(
        const float* __restrict__ e_feat,
        const float* __restrict__ W1, const float* __restrict__ b1,
        const float* __restrict__ W2, const float* __restrict__ b2,
        const float* __restrict__ W3, const float* __restrict__ b3) {
    __shared__ float sh_e[EDIM];
    __shared__ float sh_h1[HID];
    __shared__ float sh_h2[HID];
    __shared__ float sh_part[4][HID];
    __shared__ float sh_g[NC];

    const int e   = blockIdx.x;
    const int tid = threadIdx.x;
    const int o   = tid & 255;    // output unit
    const int s   = tid >> 8;     // k-slice 0..3

    if (tid < EDIM) sh_e[tid] = e_feat[e * EDIM + tid];
    __syncthreads();

    // ---- layer 1: h1 = relu(e @ W1 + b1), split-K 4x16 ----
    {
        float acc = 0.0f;
        const int k0 = s * 16;
        #pragma unroll
        for (int k = 0; k < 16; ++k)
            acc = fmaf(sh_e[k0 + k], W1[(k0 + k) * HID + o], acc);
        sh_part[s][o] = acc;
    }
    __syncthreads();
    if (tid < HID) {
        float v = sh_part[0][tid] + sh_part[1][tid] + sh_part[2][tid] + sh_part[3][tid] + b1[tid];
        sh_h1[tid] = fmaxf(v, 0.0f);
    }
    __syncthreads();

    // ---- layer 2: h2 = relu(h1 @ W2 + b2), split-K 4x64 ----
    {
        float acc = 0.0f;
        const int k0 = s * 64;
        #pragma unroll 8
        for (int k = 0; k < 64; ++k)
            acc = fmaf(sh_h1[k0 + k], W2[(k0 + k) * HID + o], acc);
        sh_part[s][o] = acc;
    }
    __syncthreads();
    if (tid < HID) {
        float v = sh_part[0][tid] + sh_part[1][tid] + sh_part[2][tid] + sh_part[3][tid] + b2[tid];
        sh_h2[tid] = fmaxf(v, 0.0f);
    }
    __syncthreads();

    // ---- layer 3: g = h2 @ W3 + b3, split-K 4x64 over 112 outputs ----
    if (o < NC) {
        float acc = 0.0f;
        const int k0 = s * 64;
        #pragma unroll 8
        for (int k = 0; k < 64; ++k)
            acc = fmaf(sh_h2[k0 + k], W3[(k0 + k) * NC + o], acc);
        sh_part[s][o] = acc;
    }
    __syncthreads();
    if (tid < NC) {
        sh_g[tid] = sh_part[0][tid] + sh_part[1][tid] + sh_part[2][tid] + sh_part[3][tid] + b3[tid];
    }
    __syncthreads();

    // Expand 112 -> 240 via GATE_IDX into global scratch
    if (tid < D) g_gf[e * D + tid] = sh_g[gate_idx(tid)];
}

// ---------------- Kernel 2: streaming broadcast multiply --------------------
// out[m, e, d] = x[m, d] * gf[e, d]
// 1024 threads = 16 e-groups x 64 lanes (lane<60 active). Each thread owns a
// fixed d4 lane: x held in a register per m, inner loop = LDS + FMUL + STG.
__global__ void __launch_bounds__(1024, 2) bcast_kernel(const float* __restrict__ x,
                                                        float* __restrict__ out) {
    extern __shared__ float4 sh_gf4[];   // NE*D4 = 6000 float4 = 96 KB
    const float4* gf4 = reinterpret_cast<const float4*>(g_gf);

    for (int i = threadIdx.x; i < NE * D4; i += blockDim.x)
        sh_gf4[i] = gf4[i];
    __syncthreads();

    const int lane = threadIdx.x & 63;   // d4 lane (0..63, <60 active)
    const int eg   = threadIdx.x >> 6;   // e-group 0..15

    if (lane >= D4) return;

    const float4* x4   = reinterpret_cast<const float4*>(x);
    float4*       out4 = reinterpret_cast<float4*>(out);

    for (int m = blockIdx.x; m < MROWS; m += GRID2) {
        const float4 xv = __ldg(&x4[m * D4 + lane]);
        float4* __restrict__ orow = out4 + (size_t)m * (NE * D4) + lane;
        #pragma unroll 2
        for (int e = eg; e < NE; e += 16) {
            const float4 g = sh_gf4[e * D4 + lane];
            float4 r;
            r.x = g.x * xv.x;
            r.y = g.y * xv.y;
            r.z = g.z * xv.z;
            r.w = g.w * xv.w;
            __stcs(&orow[e * D4], r);    // streaming store, evict-first
        }
    }
}

extern "C" void kernel_launch(void* const* d_in, const int* in_sizes, int n_in,
                              void* d_out, int out_size) {
    const float* x      = (const float*)d_in[0];
    const float* e_feat = (const float*)d_in[1];
    const float* W1     = (const float*)d_in[2];
    const float* b1     = (const float*)d_in[3];
    const float* W2     = (const float*)d_in[4];
    const float* b2     = (const float*)d_in[5];
    const float* W3     = (const float*)d_in[6];
    const float* b3     = (const float*)d_in[7];
    float* out = (float*)d_out;

    mlp_kernel<<<NE, 1024>>>(e_feat, W1, b1, W2, b2, W3, b3);

    const int smem = NE * D * (int)sizeof(float);   // 96000 bytes
    cudaFuncSetAttribute(bcast_kernel, cudaFuncAttributeMaxDynamicSharedMemorySize, smem);
    bcast_kernel<<<GRID2, 1024, smem>>>(x, out);
}